// round 11
// baseline (speedup 1.0000x reference)
#include <cuda_runtime.h>
#include <math.h>

// Problem constants
#define B    16
#define SQ   128
#define SK   256
#define HID  128
#define H    4
#define DK   32
#define DIM  64
#define OUT  128

// Intermediate scratch (no cudaMalloc allowed)
__device__ float g_qp[B * SQ * HID];
__device__ float g_kp[B * SK * HID];
__device__ float g_x [B * SQ * (H * DIM)];

// ---- tf32 helpers ----
__device__ __forceinline__ float tf32f(float x) {
    unsigned u;
    asm("cvt.rna.tf32.f32 %0, %1;" : "=r"(u) : "f"(x));
    return __uint_as_float(u);
}
__device__ __forceinline__ void mma_tf32(float* d, const unsigned* a, const unsigned* b) {
    asm volatile(
        "mma.sync.aligned.m16n8k8.row.col.f32.tf32.tf32.f32 "
        "{%0,%1,%2,%3}, {%4,%5,%6,%7}, {%8,%9}, {%0,%1,%2,%3};"
        : "+f"(d[0]), "+f"(d[1]), "+f"(d[2]), "+f"(d[3])
        : "r"(a[0]), "r"(a[1]), "r"(a[2]), "r"(a[3]), "r"(b[0]), "r"(b[1]));
}

// ---------------------------------------------------------------------------
// tf32 split-precision projection GEMM: C[M,128] = A[M,KDIM] @ W[128,KDIM]^T + b
// 3xTF32: x = hi + lo; D += Ah*Wh + Ah*Wl + Al*Wh  (error ~2^-22, fp32-grade).
// Block: 256 threads, MT rows x full N=128, K chunked by 32.
// smem pitches PM=40 / PW=136 (== 8 mod 32 -> conflict-free fragment LDS).
// ---------------------------------------------------------------------------
#define PM 40
#define PW 136
#define SMEM_PROJ ((2 * 32 * PM + 2 * 32 * PW) * (int)sizeof(float))  // 45.0 KB

template<int MT, int KDIM>
__device__ __forceinline__ void mma_gemm_body(const float* __restrict__ A,
                                              const float* __restrict__ W,
                                              const float* __restrict__ bias,
                                              float* __restrict__ C,
                                              int row0, float* sm) {
    float* Ah = sm;                  // 32 * PM
    float* Al = Ah + 32 * PM;
    float* Wh = Al + 32 * PM;        // 32 * PW
    float* Wl = Wh + 32 * PW;
    const unsigned* Ahu = (const unsigned*)Ah;
    const unsigned* Alu = (const unsigned*)Al;
    const unsigned* Whu = (const unsigned*)Wh;
    const unsigned* Wlu = (const unsigned*)Wl;

    const int t    = threadIdx.x;
    const int lane = t & 31;
    const int w    = t >> 5;         // 0..7, warp w covers n [w*16, w*16+16)
    const int lr   = lane >> 2;      // 0..7
    const int lc   = lane & 3;       // 0..3
    const int n0   = w * 16;

    constexpr int NMT = MT / 16;
    float d[NMT][2][4];
    #pragma unroll
    for (int i = 0; i < NMT; i++)
        #pragma unroll
        for (int j = 0; j < 2; j++)
            #pragma unroll
            for (int r = 0; r < 4; r++) d[i][j][r] = 0.f;

    #pragma unroll 1
    for (int kc = 0; kc < KDIM / 32; kc++) {
        if (kc) __syncthreads();
        // stage A chunk (MT rows x 32 k) -> [k][m] hi/lo
        if (t < MT * 8) {
            const int m  = t & (MT - 1);
            const int k4 = (t / MT) * 4;
            float4 v = *(const float4*)(A + (row0 + m) * KDIM + kc * 32 + k4);
            float h, l;
            h = tf32f(v.x); l = tf32f(v.x - h);
            Ah[(k4 + 0) * PM + m] = h; Al[(k4 + 0) * PM + m] = l;
            h = tf32f(v.y); l = tf32f(v.y - h);
            Ah[(k4 + 1) * PM + m] = h; Al[(k4 + 1) * PM + m] = l;
            h = tf32f(v.z); l = tf32f(v.z - h);
            Ah[(k4 + 2) * PM + m] = h; Al[(k4 + 2) * PM + m] = l;
            h = tf32f(v.w); l = tf32f(v.w - h);
            Ah[(k4 + 3) * PM + m] = h; Al[(k4 + 3) * PM + m] = l;
        }
        // stage W chunk (128 n x 32 k) -> [k][n] hi/lo
        #pragma unroll
        for (int j = 0; j < 4; j++) {
            const int id = t + j * 256;
            const int n  = id & 127;
            const int k4 = (id >> 7) * 4;
            float4 v = *(const float4*)(W + n * KDIM + kc * 32 + k4);
            float h, l;
            h = tf32f(v.x); l = tf32f(v.x - h);
            Wh[(k4 + 0) * PW + n] = h; Wl[(k4 + 0) * PW + n] = l;
            h = tf32f(v.y); l = tf32f(v.y - h);
            Wh[(k4 + 1) * PW + n] = h; Wl[(k4 + 1) * PW + n] = l;
            h = tf32f(v.z); l = tf32f(v.z - h);
            Wh[(k4 + 2) * PW + n] = h; Wl[(k4 + 2) * PW + n] = l;
            h = tf32f(v.w); l = tf32f(v.w - h);
            Wh[(k4 + 3) * PW + n] = h; Wl[(k4 + 3) * PW + n] = l;
        }
        __syncthreads();

        #pragma unroll
        for (int ks = 0; ks < 4; ks++) {
            const int k0 = ks * 8;
            unsigned ah[NMT][4], al[NMT][4];
            #pragma unroll
            for (int i = 0; i < NMT; i++) {
                const int ea = (k0 + lc) * PM + i * 16 + lr;
                const int eb = (k0 + 4 + lc) * PM + i * 16 + lr;
                ah[i][0] = Ahu[ea];  ah[i][1] = Ahu[ea + 8];
                ah[i][2] = Ahu[eb];  ah[i][3] = Ahu[eb + 8];
                al[i][0] = Alu[ea];  al[i][1] = Alu[ea + 8];
                al[i][2] = Alu[eb];  al[i][3] = Alu[eb + 8];
            }
            unsigned bh[2][2], bl[2][2];
            #pragma unroll
            for (int j = 0; j < 2; j++) {
                const int ba = (k0 + lc) * PW + n0 + j * 8 + lr;
                bh[j][0] = Whu[ba];  bh[j][1] = Whu[ba + 4 * PW];
                bl[j][0] = Wlu[ba];  bl[j][1] = Wlu[ba + 4 * PW];
            }
            #pragma unroll
            for (int i = 0; i < NMT; i++)
                #pragma unroll
                for (int j = 0; j < 2; j++) {
                    mma_tf32(d[i][j], ah[i], bh[j]);
                    mma_tf32(d[i][j], ah[i], bl[j]);
                    mma_tf32(d[i][j], al[i], bh[j]);
                }
        }
    }

    #pragma unroll
    for (int i = 0; i < NMT; i++)
        #pragma unroll
        for (int j = 0; j < 2; j++) {
            const int col = n0 + j * 8 + lc * 2;
            const float2 b2 = *(const float2*)(bias + col);
            const int ra = row0 + i * 16 + lr;
            float2 o0, o1;
            o0.x = d[i][j][0] + b2.x; o0.y = d[i][j][1] + b2.y;
            o1.x = d[i][j][2] + b2.x; o1.y = d[i][j][3] + b2.y;
            *(float2*)(C + ra * 128 + col) = o0;
            *(float2*)(C + (ra + 8) * 128 + col) = o1;
        }
}

// Q-proj (2048 rows -> 64 blocks) + K-proj (4096 rows -> 128 blocks)
__global__ __launch_bounds__(256) void qk_proj_kernel(
        const float* __restrict__ q,  const float* __restrict__ Wq,
        const float* __restrict__ bq, float* __restrict__ qp,
        const float* __restrict__ k,  const float* __restrict__ Wk,
        const float* __restrict__ bk, float* __restrict__ kp) {
    extern __shared__ float sm[];
    if (blockIdx.x < 64)
        mma_gemm_body<32, 128>(q, Wq, bq, qp, blockIdx.x * 32, sm);
    else
        mma_gemm_body<32, 128>(k, Wk, bk, kp, (blockIdx.x - 64) * 32, sm);
}

// O-proj: 2048 rows, MT=16 -> 128 blocks
__global__ __launch_bounds__(256) void o_proj_kernel(
        const float* __restrict__ x,  const float* __restrict__ Wo,
        const float* __restrict__ bo, float* __restrict__ out) {
    extern __shared__ float sm[];
    mma_gemm_body<16, 256>(x, Wo, bo, out, blockIdx.x * 16, sm);
}

// ---------------------------------------------------------------------------
// Fused masked attention (unchanged from measured-best R8).
// ---------------------------------------------------------------------------
#define QT 32
#define EP 36    // e_t pitch [k][q]
#define KP 33    // staged K pitch (phase 1)
#define VP 132   // vm pitch [k][n]

__global__ __launch_bounds__(256) void attn_kernel(
        const float* __restrict__ qp,
        const float* __restrict__ kp,
        const float* __restrict__ value,
        const int*   __restrict__ mask,
        float* __restrict__ xout) {
    extern __shared__ float sm[];
    float* q_s = sm;                        // 32*32  = 1024
    float* e_t = sm + QT * 32;              // 256*36 = 9216
    float* buf = e_t + SK * EP;             // 256*33 = 8448 (K tile, then vm 64*132)

    const int blk = blockIdx.x;
    const int qt  = blk & 3;
    const int h   = (blk >> 2) & 3;
    const int b   = blk >> 4;
    const int q0  = qt * QT;
    const int tid = threadIdx.x;

    for (int idx = tid; idx < QT * 32; idx += 256) {
        int r = idx >> 5, i = idx & 31;
        q_s[idx] = qp[(b * SQ + q0 + r) * HID + h * DK + i];
    }
    for (int idx = tid; idx < SK * 32; idx += 256) {
        int kk = idx >> 5, i = idx & 31;
        buf[kk * KP + i] = kp[(b * SK + kk) * HID + h * DK + i];
    }
    __syncthreads();

    // Phase 1: one thread per k column -> e_t[k][q] (tf32-rounded)
    {
        const int kk = tid;
        float kreg[32];
        #pragma unroll
        for (int i = 0; i < 32; i++) kreg[i] = buf[kk * KP + i];
        const float scale = 0.17677669529663687f;   // 1/sqrt(32)
        #pragma unroll 4
        for (int r = 0; r < QT; r++) {
            float acc = 0.f;
            #pragma unroll
            for (int i = 0; i < 32; i++)
                acc = fmaf(q_s[r * 32 + i], kreg[i], acc);
            e_t[kk * EP + r] = tf32f(__expf(acc * scale));
        }
    }

    // Phase 2: tf32 MMA. 8 warps; warp w covers n-cols [w*16, w*16+16).
    const int lane = tid & 31;
    const int w    = tid >> 5;
    const int lr   = lane >> 2;
    const int lc   = lane & 3;
    const int nb   = w * 16;

    float d[2][2][4];
    #pragma unroll
    for (int i = 0; i < 2; i++)
        #pragma unroll
        for (int j = 0; j < 2; j++)
            #pragma unroll
            for (int r = 0; r < 4; r++) d[i][j][r] = 0.f;

    const unsigned* eu = (const unsigned*)e_t;
    const unsigned* vu = (const unsigned*)buf;

    #pragma unroll 1
    for (int c = 0; c < 4; c++) {
        __syncthreads();
        #pragma unroll
        for (int it = 0; it < 8; it++) {
            int item = tid + it * 256;
            int lk = item >> 5, d2 = item & 31;
            int gbase = (b * SK + c * 64 + lk) * DIM + d2 * 2;
            float2 v = *(const float2*)(value + gbase);
            int2  mm = *(const int2*)(mask + gbase);
            float4 wv;
            wv.x = mm.x ? tf32f(v.x) : 0.f;  wv.y = mm.x ? 1.f : 0.f;
            wv.z = mm.y ? tf32f(v.y) : 0.f;  wv.w = mm.y ? 1.f : 0.f;
            *(float4*)(buf + lk * VP + d2 * 4) = wv;
        }
        __syncthreads();

        #pragma unroll
        for (int ks = 0; ks < 8; ks++) {
            const int k0 = c * 64 + ks * 8;
            unsigned a[2][4];
            const int ea = (k0 + lc) * EP + lr;
            const int eb = (k0 + 4 + lc) * EP + lr;
            #pragma unroll
            for (int i = 0; i < 2; i++) {
                a[i][0] = eu[ea + i * 16];
                a[i][1] = eu[ea + i * 16 + 8];
                a[i][2] = eu[eb + i * 16];
                a[i][3] = eu[eb + i * 16 + 8];
            }
            unsigned bf[2][2];
            const int ba = (ks * 8 + lc) * VP + nb + lr;
            #pragma unroll
            for (int j = 0; j < 2; j++) {
                bf[j][0] = vu[ba + j * 8];
                bf[j][1] = vu[ba + j * 8 + 4 * VP];
            }
            #pragma unroll
            for (int i = 0; i < 2; i++)
                #pragma unroll
                for (int j = 0; j < 2; j++)
                    mma_tf32(d[i][j], a[i], bf[j]);
        }
    }

    #pragma unroll
    for (int j = 0; j < 2; j++) {
        const int ch = w * 8 + j * 4 + lc;
        bool bad = false;
        #pragma unroll
        for (int i = 0; i < 2; i++)
            if (d[i][j][1] == 0.f || d[i][j][3] == 0.f) bad = true;
        float vs = 0.f;
        if (bad) {
            for (int kk = 0; kk < SK; kk++)
                vs += value[(b * SK + kk) * DIM + ch];
            vs *= (1.0f / 256.0f);
        }
        #pragma unroll
        for (int i = 0; i < 2; i++) {
            const int ra = i * 16 + lr;
            const int rb = ra + 8;
            float xa = (d[i][j][1] > 0.f) ? (d[i][j][0] / d[i][j][1]) : vs;
            float xb = (d[i][j][3] > 0.f) ? (d[i][j][2] / d[i][j][3]) : vs;
            xout[(b * SQ + q0 + ra) * (H * DIM) + h * DIM + ch] = xa;
            xout[(b * SQ + q0 + rb) * (H * DIM) + h * DIM + ch] = xb;
        }
    }
}

// ---------------------------------------------------------------------------
extern "C" void kernel_launch(void* const* d_in, const int* in_sizes, int n_in,
                              void* d_out, int out_size) {
    const float* query = (const float*)d_in[0];
    const float* key   = (const float*)d_in[1];
    const float* value = (const float*)d_in[2];
    const int*   mask  = (const int*)  d_in[3];
    const float* Wq    = (const float*)d_in[4];
    const float* bq    = (const float*)d_in[5];
    const float* Wk    = (const float*)d_in[6];
    const float* bk    = (const float*)d_in[7];
    const float* Wo    = (const float*)d_in[8];
    const float* bo    = (const float*)d_in[9];
    float* out = (float*)d_out;

    float* qp; cudaGetSymbolAddress((void**)&qp, g_qp);
    float* kp; cudaGetSymbolAddress((void**)&kp, g_kp);
    float* xb; cudaGetSymbolAddress((void**)&xb, g_x);

    const int smem_attn = (QT * 32 + SK * EP + SK * KP) * (int)sizeof(float); // ~74.8KB
    cudaFuncSetAttribute(attn_kernel,    cudaFuncAttributeMaxDynamicSharedMemorySize, smem_attn);
    cudaFuncSetAttribute(qk_proj_kernel, cudaFuncAttributeMaxDynamicSharedMemorySize, SMEM_PROJ);
    cudaFuncSetAttribute(o_proj_kernel,  cudaFuncAttributeMaxDynamicSharedMemorySize, SMEM_PROJ);

    // Q (2048x128x128) + K (4096x128x128) projection: 192 blocks, tensor cores
    qk_proj_kernel<<<192, 256, SMEM_PROJ>>>(query, Wq, bq, qp, key, Wk, bk, kp);
    // fused attention: 256 blocks
    attn_kernel<<<B * H * (SQ / QT), 256, smem_attn>>>(qp, kp, value, mask, xb);
    // output projection: 2048x128x256, 128 blocks, tensor cores
    o_proj_kernel<<<128, 256, SMEM_PROJ>>>(xb, Wo, bo, out);
}

// round 14
// speedup vs baseline: 1.8609x; 1.8609x over previous
#include <cuda_runtime.h>
#include <math.h>

// Problem constants
#define B    16
#define SQ   128
#define SK   256
#define HID  128
#define H    4
#define DK   32
#define DIM  64
#define OUT  128

// Intermediate scratch (no cudaMalloc allowed)
__device__ float g_qp[B * SQ * HID];
__device__ float g_kp[B * SK * HID];
__device__ float g_x [B * SQ * (H * DIM)];

// ---- tf32 helpers ----
__device__ __forceinline__ float tf32f(float x) {
    unsigned u;
    asm("cvt.rna.tf32.f32 %0, %1;" : "=r"(u) : "f"(x));
    return __uint_as_float(u);
}
__device__ __forceinline__ void mma_tf32(float* d, const unsigned* a, const unsigned* b) {
    asm volatile(
        "mma.sync.aligned.m16n8k8.row.col.f32.tf32.tf32.f32 "
        "{%0,%1,%2,%3}, {%4,%5,%6,%7}, {%8,%9}, {%0,%1,%2,%3};"
        : "+f"(d[0]), "+f"(d[1]), "+f"(d[2]), "+f"(d[3])
        : "r"(a[0]), "r"(a[1]), "r"(a[2]), "r"(a[3]), "r"(b[0]), "r"(b[1]));
}

// ---------------------------------------------------------------------------
// Register-blocked SIMT GEMM (R4 measured-best): C[M,128]=A@W^T+bias
// Block tile 32x64, 128 threads, 4x4 per thread.
// ---------------------------------------------------------------------------
template<int KDIM>
__device__ __forceinline__ void gemm_body(const float* __restrict__ A,
                                          const float* __restrict__ W,
                                          const float* __restrict__ bias,
                                          float* __restrict__ C,
                                          int tile, float* As, float* Bs) {
    const int t  = threadIdx.x;      // 0..127
    const int ty = t >> 4;           // 0..7  -> rows ty*4..+3
    const int tx = t & 15;           // 0..15 -> cols tx*4..+3
    const int row0 = (tile >> 1) * 32;
    const int col0 = (tile & 1) * 64;

    const float4 bias4 = *(const float4*)(bias + col0 + tx * 4);

    float acc[4][4];
    #pragma unroll
    for (int i = 0; i < 4; i++)
        #pragma unroll
        for (int j = 0; j < 4; j++) acc[i][j] = 0.f;

    const int lmA = t >> 2;          // 0..31
    const int lkA = (t & 3) * 4;     // 0,4,8,12
    const int lnB = t >> 1;          // 0..63
    const int lkB = (t & 1) * 8;     // 0,8

    for (int kt = 0; kt < KDIM / 16; kt++) {
        float4 av = *(const float4*)(A + (row0 + lmA) * KDIM + kt * 16 + lkA);
        As[(lkA + 0) * 32 + lmA] = av.x;
        As[(lkA + 1) * 32 + lmA] = av.y;
        As[(lkA + 2) * 32 + lmA] = av.z;
        As[(lkA + 3) * 32 + lmA] = av.w;
        float4 b0 = *(const float4*)(W + (col0 + lnB) * KDIM + kt * 16 + lkB);
        float4 b1 = *(const float4*)(W + (col0 + lnB) * KDIM + kt * 16 + lkB + 4);
        Bs[(lkB + 0) * 64 + lnB] = b0.x;
        Bs[(lkB + 1) * 64 + lnB] = b0.y;
        Bs[(lkB + 2) * 64 + lnB] = b0.z;
        Bs[(lkB + 3) * 64 + lnB] = b0.w;
        Bs[(lkB + 4) * 64 + lnB] = b1.x;
        Bs[(lkB + 5) * 64 + lnB] = b1.y;
        Bs[(lkB + 6) * 64 + lnB] = b1.z;
        Bs[(lkB + 7) * 64 + lnB] = b1.w;
        __syncthreads();

        #pragma unroll
        for (int kk = 0; kk < 16; kk++) {
            float4 a = *(const float4*)(As + kk * 32 + ty * 4);
            float4 b = *(const float4*)(Bs + kk * 64 + tx * 4);
            acc[0][0] = fmaf(a.x, b.x, acc[0][0]);
            acc[0][1] = fmaf(a.x, b.y, acc[0][1]);
            acc[0][2] = fmaf(a.x, b.z, acc[0][2]);
            acc[0][3] = fmaf(a.x, b.w, acc[0][3]);
            acc[1][0] = fmaf(a.y, b.x, acc[1][0]);
            acc[1][1] = fmaf(a.y, b.y, acc[1][1]);
            acc[1][2] = fmaf(a.y, b.z, acc[1][2]);
            acc[1][3] = fmaf(a.y, b.w, acc[1][3]);
            acc[2][0] = fmaf(a.z, b.x, acc[2][0]);
            acc[2][1] = fmaf(a.z, b.y, acc[2][1]);
            acc[2][2] = fmaf(a.z, b.z, acc[2][2]);
            acc[2][3] = fmaf(a.z, b.w, acc[2][3]);
            acc[3][0] = fmaf(a.w, b.x, acc[3][0]);
            acc[3][1] = fmaf(a.w, b.y, acc[3][1]);
            acc[3][2] = fmaf(a.w, b.z, acc[3][2]);
            acc[3][3] = fmaf(a.w, b.w, acc[3][3]);
        }
        __syncthreads();
    }

    #pragma unroll
    for (int i = 0; i < 4; i++) {
        float4 o;
        o.x = acc[i][0] + bias4.x;
        o.y = acc[i][1] + bias4.y;
        o.z = acc[i][2] + bias4.z;
        o.w = acc[i][3] + bias4.w;
        *(float4*)(C + (row0 + ty * 4 + i) * 128 + col0 + tx * 4) = o;
    }
}

__global__ __launch_bounds__(128) void qk_proj_kernel(
        const float* __restrict__ q,  const float* __restrict__ Wq,
        const float* __restrict__ bq, float* __restrict__ qp,
        const float* __restrict__ k,  const float* __restrict__ Wk,
        const float* __restrict__ bk, float* __restrict__ kp) {
    __shared__ float As[16 * 32];
    __shared__ float Bs[16 * 64];
    if (blockIdx.x < 128)
        gemm_body<128>(q, Wq, bq, qp, blockIdx.x, As, Bs);
    else
        gemm_body<128>(k, Wk, bk, kp, blockIdx.x - 128, As, Bs);
}

__global__ __launch_bounds__(128) void o_proj_kernel(
        const float* __restrict__ x,  const float* __restrict__ Wo,
        const float* __restrict__ bo, float* __restrict__ out) {
    __shared__ float As[16 * 32];
    __shared__ float Bs[16 * 64];
    gemm_body<256>(x, Wo, bo, out, blockIdx.x, As, Bs);
}

// ---------------------------------------------------------------------------
// Fused masked attention. Grid: B*H*(SQ/32) = 256 blocks, 256 threads.
// Phase 1 (tf32 MMA): D[256k x 32q] = K[256x32] @ Qt[32x32];
//   e_t[k][q] = tf32(exp(D*scale)). A-frags from k_s (pitch 36, conflict-free),
//   B-frags from transposed q_t, D epilogue -> STS.64 pairs.
// Phase 2 (tf32 MMA, unchanged from R8 win): (num|den) = e @ vm, interleaved n.
// ---------------------------------------------------------------------------
#define QT 32
#define EP 36    // e_t pitch [k][q]
#define KSP 36   // k_s pitch [k][dk]
#define QP 36    // q_t pitch [dk][q]
#define VP 132   // vm pitch [k][n]

__global__ __launch_bounds__(256) void attn_kernel(
        const float* __restrict__ qp,
        const float* __restrict__ kp,
        const float* __restrict__ value,
        const int*   __restrict__ mask,
        float* __restrict__ xout) {
    extern __shared__ float sm[];
    float* q_t = sm;                        // 32*36  = 1152 (Q transposed [dk][q])
    float* e_t = q_t + 32 * QP;             // 256*36 = 9216
    float* k_s = e_t + SK * EP;             // 256*36 = 9216 (K tile; reused as vm)

    const int blk = blockIdx.x;
    const int qt  = blk & 3;
    const int h   = (blk >> 2) & 3;
    const int b   = blk >> 4;
    const int q0  = qt * QT;
    const int tid = threadIdx.x;
    const int lane = tid & 31;
    const int w    = tid >> 5;    // 0..7
    const int lr   = lane >> 2;   // 0..7
    const int lc   = lane & 3;    // 0..3

    // stage Q transposed: q_t[dk][q], tf32-rounded
    #pragma unroll
    for (int it = 0; it < 4; it++) {
        int i = (tid >> 5) + it * 8;        // dk index
        int r = tid & 31;                   // q row
        q_t[i * QP + r] = tf32f(qp[(b * SQ + q0 + r) * HID + h * DK + i]);
    }
    // stage K tile: k_s[k][dk], tf32-rounded, pitch 36
    for (int idx = tid; idx < SK * 32; idx += 256) {
        int kk = idx >> 5, i = idx & 31;
        k_s[kk * KSP + i] = tf32f(kp[(b * SK + kk) * HID + h * DK + i]);
    }
    __syncthreads();

    // ---- Phase 1: tf32 MMA scores. Warp w owns k-rows [w*32, w*32+32). ----
    {
        const int m0 = w * 32;
        const unsigned* ksu = (const unsigned*)k_s;
        const unsigned* qtu = (const unsigned*)q_t;
        float dsc[2][4][4];
        #pragma unroll
        for (int mi = 0; mi < 2; mi++)
            #pragma unroll
            for (int nj = 0; nj < 4; nj++)
                #pragma unroll
                for (int r = 0; r < 4; r++) dsc[mi][nj][r] = 0.f;

        #pragma unroll
        for (int ks = 0; ks < 4; ks++) {
            const int k0 = ks * 8;
            unsigned a[2][4], bq[4][2];
            #pragma unroll
            for (int mi = 0; mi < 2; mi++) {
                const int ra = (m0 + mi * 16 + lr) * KSP + k0 + lc;
                const int rb = (m0 + mi * 16 + lr + 8) * KSP + k0 + lc;
                a[mi][0] = ksu[ra];
                a[mi][1] = ksu[rb];
                a[mi][2] = ksu[ra + 4];
                a[mi][3] = ksu[rb + 4];
            }
            #pragma unroll
            for (int nj = 0; nj < 4; nj++) {
                bq[nj][0] = qtu[(k0 + lc) * QP + nj * 8 + lr];
                bq[nj][1] = qtu[(k0 + 4 + lc) * QP + nj * 8 + lr];
            }
            #pragma unroll
            for (int mi = 0; mi < 2; mi++)
                #pragma unroll
                for (int nj = 0; nj < 4; nj++)
                    mma_tf32(dsc[mi][nj], a[mi], bq[nj]);
        }

        const float scale = 0.17677669529663687f;   // 1/sqrt(32)
        #pragma unroll
        for (int mi = 0; mi < 2; mi++)
            #pragma unroll
            for (int nj = 0; nj < 4; nj++) {
                const int row = m0 + mi * 16 + lr;
                const int col = nj * 8 + lc * 2;
                float2 e0, e1;
                e0.x = tf32f(__expf(dsc[mi][nj][0] * scale));
                e0.y = tf32f(__expf(dsc[mi][nj][1] * scale));
                e1.x = tf32f(__expf(dsc[mi][nj][2] * scale));
                e1.y = tf32f(__expf(dsc[mi][nj][3] * scale));
                *(float2*)(e_t + row * EP + col) = e0;
                *(float2*)(e_t + (row + 8) * EP + col) = e1;
            }
    }

    // ---- Phase 2: tf32 MMA contraction (unchanged). Warp w covers n [w*16,+16). ----
    const int nb = w * 16;
    float d[2][2][4];
    #pragma unroll
    for (int i = 0; i < 2; i++)
        #pragma unroll
        for (int j = 0; j < 2; j++)
            #pragma unroll
            for (int r = 0; r < 4; r++) d[i][j][r] = 0.f;

    const unsigned* eu = (const unsigned*)e_t;
    const unsigned* vu = (const unsigned*)k_s;   // vm reuses K-tile region
    float* vmf = k_s;

    #pragma unroll 1
    for (int c = 0; c < 4; c++) {
        __syncthreads();                    // phase-1 k_s reads / prev chunk consumed
        #pragma unroll
        for (int it = 0; it < 8; it++) {
            int item = tid + it * 256;
            int lk = item >> 5, d2 = item & 31;
            int gbase = (b * SK + c * 64 + lk) * DIM + d2 * 2;
            float2 v = *(const float2*)(value + gbase);
            int2  mm = *(const int2*)(mask + gbase);
            float4 wv;
            wv.x = mm.x ? tf32f(v.x) : 0.f;  wv.y = mm.x ? 1.f : 0.f;
            wv.z = mm.y ? tf32f(v.y) : 0.f;  wv.w = mm.y ? 1.f : 0.f;
            *(float4*)(vmf + lk * VP + d2 * 4) = wv;
        }
        __syncthreads();

        #pragma unroll
        for (int ks = 0; ks < 8; ks++) {
            const int k0 = c * 64 + ks * 8;
            unsigned a[2][4];
            const int ea = (k0 + lc) * EP + lr;
            const int eb = (k0 + 4 + lc) * EP + lr;
            #pragma unroll
            for (int i = 0; i < 2; i++) {
                a[i][0] = eu[ea + i * 16];
                a[i][1] = eu[ea + i * 16 + 8];
                a[i][2] = eu[eb + i * 16];
                a[i][3] = eu[eb + i * 16 + 8];
            }
            unsigned bf[2][2];
            const int ba = (ks * 8 + lc) * VP + nb + lr;
            #pragma unroll
            for (int j = 0; j < 2; j++) {
                bf[j][0] = vu[ba + j * 8];
                bf[j][1] = vu[ba + j * 8 + 4 * VP];
            }
            #pragma unroll
            for (int i = 0; i < 2; i++)
                #pragma unroll
                for (int j = 0; j < 2; j++)
                    mma_tf32(d[i][j], a[i], bf[j]);
        }
    }

    // Epilogue: x = num/den (den==0 fallback: mean(value))
    #pragma unroll
    for (int j = 0; j < 2; j++) {
        const int ch = w * 8 + j * 4 + lc;
        bool bad = false;
        #pragma unroll
        for (int i = 0; i < 2; i++)
            if (d[i][j][1] == 0.f || d[i][j][3] == 0.f) bad = true;
        float vs = 0.f;
        if (bad) {
            for (int kk = 0; kk < SK; kk++)
                vs += value[(b * SK + kk) * DIM + ch];
            vs *= (1.0f / 256.0f);
        }
        #pragma unroll
        for (int i = 0; i < 2; i++) {
            const int ra = i * 16 + lr;
            const int rb = ra + 8;
            float xa = (d[i][j][1] > 0.f) ? (d[i][j][0] / d[i][j][1]) : vs;
            float xb = (d[i][j][3] > 0.f) ? (d[i][j][2] / d[i][j][3]) : vs;
            xout[(b * SQ + q0 + ra) * (H * DIM) + h * DIM + ch] = xa;
            xout[(b * SQ + q0 + rb) * (H * DIM) + h * DIM + ch] = xb;
        }
    }
}

// ---------------------------------------------------------------------------
extern "C" void kernel_launch(void* const* d_in, const int* in_sizes, int n_in,
                              void* d_out, int out_size) {
    const float* query = (const float*)d_in[0];
    const float* key   = (const float*)d_in[1];
    const float* value = (const float*)d_in[2];
    const int*   mask  = (const int*)  d_in[3];
    const float* Wq    = (const float*)d_in[4];
    const float* bq    = (const float*)d_in[5];
    const float* Wk    = (const float*)d_in[6];
    const float* bk    = (const float*)d_in[7];
    const float* Wo    = (const float*)d_in[8];
    const float* bo    = (const float*)d_in[9];
    float* out = (float*)d_out;

    float* qp; cudaGetSymbolAddress((void**)&qp, g_qp);
    float* kp; cudaGetSymbolAddress((void**)&kp, g_kp);
    float* xb; cudaGetSymbolAddress((void**)&xb, g_x);

    const int smem_attn = (32 * QP + SK * EP + SK * KSP) * (int)sizeof(float); // 78.3 KB
    cudaFuncSetAttribute(attn_kernel, cudaFuncAttributeMaxDynamicSharedMemorySize, smem_attn);

    // Q (2048x128x128) + K (4096x128x128) projection: 384 blocks (SIMT, measured best)
    qk_proj_kernel<<<384, 128>>>(query, Wq, bq, qp, key, Wk, bk, kp);
    // fused attention: 256 blocks
    attn_kernel<<<B * H * (SQ / QT), 256, smem_attn>>>(qp, kp, value, mask, xb);
    // output projection: 2048x128x256
    o_proj_kernel<<<128, 128>>>(xb, Wo, bo, out);
}

// round 17
// speedup vs baseline: 1.9371x; 1.0410x over previous
#include <cuda_runtime.h>
#include <math.h>

// Problem constants
#define B    16
#define SQ   128
#define SK   256
#define HID  128
#define H    4
#define DK   32
#define DIM  64
#define OUT  128

// Intermediate scratch (no cudaMalloc allowed)
__device__ float g_qp[B * SQ * HID];
__device__ float g_kp[B * SK * HID];
__device__ float g_x [B * SQ * (H * DIM)];

// ---- tf32 helpers ----
__device__ __forceinline__ float tf32f(float x) {
    unsigned u;
    asm("cvt.rna.tf32.f32 %0, %1;" : "=r"(u) : "f"(x));
    return __uint_as_float(u);
}
__device__ __forceinline__ void mma_tf32(float* d, const unsigned* a, const unsigned* b) {
    asm volatile(
        "mma.sync.aligned.m16n8k8.row.col.f32.tf32.tf32.f32 "
        "{%0,%1,%2,%3}, {%4,%5,%6,%7}, {%8,%9}, {%0,%1,%2,%3};"
        : "+f"(d[0]), "+f"(d[1]), "+f"(d[2]), "+f"(d[3])
        : "r"(a[0]), "r"(a[1]), "r"(a[2]), "r"(a[3]), "r"(b[0]), "r"(b[1]));
}

// ---------------------------------------------------------------------------
// Register-blocked SIMT GEMM (R4 measured-best): C[M,128]=A@W^T+bias
// Block tile 32x64, 128 threads, 4x4 per thread. (qk_proj only)
// ---------------------------------------------------------------------------
template<int KDIM>
__device__ __forceinline__ void gemm_body(const float* __restrict__ A,
                                          const float* __restrict__ W,
                                          const float* __restrict__ bias,
                                          float* __restrict__ C,
                                          int tile, float* As, float* Bs) {
    const int t  = threadIdx.x;      // 0..127
    const int ty = t >> 4;           // 0..7  -> rows ty*4..+3
    const int tx = t & 15;           // 0..15 -> cols tx*4..+3
    const int row0 = (tile >> 1) * 32;
    const int col0 = (tile & 1) * 64;

    const float4 bias4 = *(const float4*)(bias + col0 + tx * 4);

    float acc[4][4];
    #pragma unroll
    for (int i = 0; i < 4; i++)
        #pragma unroll
        for (int j = 0; j < 4; j++) acc[i][j] = 0.f;

    const int lmA = t >> 2;          // 0..31
    const int lkA = (t & 3) * 4;     // 0,4,8,12
    const int lnB = t >> 1;          // 0..63
    const int lkB = (t & 1) * 8;     // 0,8

    for (int kt = 0; kt < KDIM / 16; kt++) {
        float4 av = *(const float4*)(A + (row0 + lmA) * KDIM + kt * 16 + lkA);
        As[(lkA + 0) * 32 + lmA] = av.x;
        As[(lkA + 1) * 32 + lmA] = av.y;
        As[(lkA + 2) * 32 + lmA] = av.z;
        As[(lkA + 3) * 32 + lmA] = av.w;
        float4 b0 = *(const float4*)(W + (col0 + lnB) * KDIM + kt * 16 + lkB);
        float4 b1 = *(const float4*)(W + (col0 + lnB) * KDIM + kt * 16 + lkB + 4);
        Bs[(lkB + 0) * 64 + lnB] = b0.x;
        Bs[(lkB + 1) * 64 + lnB] = b0.y;
        Bs[(lkB + 2) * 64 + lnB] = b0.z;
        Bs[(lkB + 3) * 64 + lnB] = b0.w;
        Bs[(lkB + 4) * 64 + lnB] = b1.x;
        Bs[(lkB + 5) * 64 + lnB] = b1.y;
        Bs[(lkB + 6) * 64 + lnB] = b1.z;
        Bs[(lkB + 7) * 64 + lnB] = b1.w;
        __syncthreads();

        #pragma unroll
        for (int kk = 0; kk < 16; kk++) {
            float4 a = *(const float4*)(As + kk * 32 + ty * 4);
            float4 b = *(const float4*)(Bs + kk * 64 + tx * 4);
            acc[0][0] = fmaf(a.x, b.x, acc[0][0]);
            acc[0][1] = fmaf(a.x, b.y, acc[0][1]);
            acc[0][2] = fmaf(a.x, b.z, acc[0][2]);
            acc[0][3] = fmaf(a.x, b.w, acc[0][3]);
            acc[1][0] = fmaf(a.y, b.x, acc[1][0]);
            acc[1][1] = fmaf(a.y, b.y, acc[1][1]);
            acc[1][2] = fmaf(a.y, b.z, acc[1][2]);
            acc[1][3] = fmaf(a.y, b.w, acc[1][3]);
            acc[2][0] = fmaf(a.z, b.x, acc[2][0]);
            acc[2][1] = fmaf(a.z, b.y, acc[2][1]);
            acc[2][2] = fmaf(a.z, b.z, acc[2][2]);
            acc[2][3] = fmaf(a.z, b.w, acc[2][3]);
            acc[3][0] = fmaf(a.w, b.x, acc[3][0]);
            acc[3][1] = fmaf(a.w, b.y, acc[3][1]);
            acc[3][2] = fmaf(a.w, b.z, acc[3][2]);
            acc[3][3] = fmaf(a.w, b.w, acc[3][3]);
        }
        __syncthreads();
    }

    #pragma unroll
    for (int i = 0; i < 4; i++) {
        float4 o;
        o.x = acc[i][0] + bias4.x;
        o.y = acc[i][1] + bias4.y;
        o.z = acc[i][2] + bias4.z;
        o.w = acc[i][3] + bias4.w;
        *(float4*)(C + (row0 + ty * 4 + i) * 128 + col0 + tx * 4) = o;
    }
}

__global__ __launch_bounds__(128) void qk_proj_kernel(
        const float* __restrict__ q,  const float* __restrict__ Wq,
        const float* __restrict__ bq, float* __restrict__ qp,
        const float* __restrict__ k,  const float* __restrict__ Wk,
        const float* __restrict__ bk, float* __restrict__ kp) {
    __shared__ float As[16 * 32];
    __shared__ float Bs[16 * 64];
    if (blockIdx.x < 128)
        gemm_body<128>(q, Wq, bq, qp, blockIdx.x, As, Bs);
    else
        gemm_body<128>(k, Wk, bk, kp, blockIdx.x - 128, As, Bs);
}

// ---------------------------------------------------------------------------
// O projection: out[2048,128] = x[2048,256] @ Wo[128,256]^T + bo
// 16x64 tiles -> 256 blocks (fills the chip), 128 threads, 2m x 4n per thread,
// K chunked by 32.
// ---------------------------------------------------------------------------
__global__ __launch_bounds__(128) void o_proj_kernel(
        const float* __restrict__ x,  const float* __restrict__ Wo,
        const float* __restrict__ bo, float* __restrict__ out) {
    __shared__ float As[32 * 18];   // [k][m], pitch 18
    __shared__ float Bs[32 * 64];   // [k][n]
    const int t = threadIdx.x;
    const int row0 = (blockIdx.x >> 1) * 16;
    const int col0 = (blockIdx.x & 1) * 64;
    const int ty = t >> 4;          // 0..7 -> rows ty*2..+1
    const int tx = t & 15;          // cols tx*4..+3

    float acc[2][4];
    #pragma unroll
    for (int i = 0; i < 2; i++)
        #pragma unroll
        for (int j = 0; j < 4; j++) acc[i][j] = 0.f;

    for (int kt = 0; kt < 8; kt++) {        // K chunks of 32
        // stage A: 16 rows x 32 k -> As[k][m] (128 float4, 1 per thread)
        {
            const int lm = t >> 3;          // 0..15
            const int lk = (t & 7) * 4;     // 0..28
            float4 v = *(const float4*)(x + (row0 + lm) * 256 + kt * 32 + lk);
            As[(lk + 0) * 18 + lm] = v.x;
            As[(lk + 1) * 18 + lm] = v.y;
            As[(lk + 2) * 18 + lm] = v.z;
            As[(lk + 3) * 18 + lm] = v.w;
        }
        // stage B: 64 n x 32 k -> Bs[k][n] (512 float4, 4 per thread)
        {
            const int n  = t >> 1;          // 0..63
            const int kb = (t & 1) * 16;    // 0 or 16
            #pragma unroll
            for (int j = 0; j < 4; j++) {
                float4 v = *(const float4*)(Wo + (col0 + n) * 256 + kt * 32 + kb + j * 4);
                Bs[(kb + j * 4 + 0) * 64 + n] = v.x;
                Bs[(kb + j * 4 + 1) * 64 + n] = v.y;
                Bs[(kb + j * 4 + 2) * 64 + n] = v.z;
                Bs[(kb + j * 4 + 3) * 64 + n] = v.w;
            }
        }
        __syncthreads();

        #pragma unroll
        for (int kk = 0; kk < 32; kk++) {
            float2 a = *(const float2*)(As + kk * 18 + ty * 2);
            float4 bv = *(const float4*)(Bs + kk * 64 + tx * 4);
            acc[0][0] = fmaf(a.x, bv.x, acc[0][0]);
            acc[0][1] = fmaf(a.x, bv.y, acc[0][1]);
            acc[0][2] = fmaf(a.x, bv.z, acc[0][2]);
            acc[0][3] = fmaf(a.x, bv.w, acc[0][3]);
            acc[1][0] = fmaf(a.y, bv.x, acc[1][0]);
            acc[1][1] = fmaf(a.y, bv.y, acc[1][1]);
            acc[1][2] = fmaf(a.y, bv.z, acc[1][2]);
            acc[1][3] = fmaf(a.y, bv.w, acc[1][3]);
        }
        __syncthreads();
    }

    const float4 bias4 = *(const float4*)(bo + col0 + tx * 4);
    #pragma unroll
    for (int i = 0; i < 2; i++) {
        float4 o;
        o.x = acc[i][0] + bias4.x;
        o.y = acc[i][1] + bias4.y;
        o.z = acc[i][2] + bias4.z;
        o.w = acc[i][3] + bias4.w;
        *(float4*)(out + (row0 + ty * 2 + i) * 128 + col0 + tx * 4) = o;
    }
}

// ---------------------------------------------------------------------------
// Fused masked attention. Grid: B*H*(SQ/32) = 256 blocks, 256 threads.
// Phase 1 (tf32 MMA): D[256k x 32q] = K[256x32] @ Qt[32x32];
//   e_t[k][q] = tf32(exp(D*scale)).
// Phase 2 (tf32 MMA): (num|den) = e @ vm, interleaved n; vm chunk staging with
//   REGISTER PREFETCH of next chunk's value/mask (overlaps L2 latency with MMA).
// ---------------------------------------------------------------------------
#define QT 32
#define EP 36    // e_t pitch [k][q]
#define KSP 36   // k_s pitch [k][dk]
#define QP 36    // q_t pitch [dk][q]
#define VP 132   // vm pitch [k][n]

__global__ __launch_bounds__(256) void attn_kernel(
        const float* __restrict__ qp,
        const float* __restrict__ kp,
        const float* __restrict__ value,
        const int*   __restrict__ mask,
        float* __restrict__ xout) {
    extern __shared__ float sm[];
    float* q_t = sm;                        // 32*36  = 1152 (Q transposed [dk][q])
    float* e_t = q_t + 32 * QP;             // 256*36 = 9216
    float* k_s = e_t + SK * EP;             // 256*36 = 9216 (K tile; reused as vm)

    const int blk = blockIdx.x;
    const int qt  = blk & 3;
    const int h   = (blk >> 2) & 3;
    const int b   = blk >> 4;
    const int q0  = qt * QT;
    const int tid = threadIdx.x;
    const int lane = tid & 31;
    const int w    = tid >> 5;    // 0..7
    const int lr   = lane >> 2;   // 0..7
    const int lc   = lane & 3;    // 0..3

    // stage Q transposed: q_t[dk][q], tf32-rounded
    #pragma unroll
    for (int it = 0; it < 4; it++) {
        int i = (tid >> 5) + it * 8;        // dk index
        int r = tid & 31;                   // q row
        q_t[i * QP + r] = tf32f(qp[(b * SQ + q0 + r) * HID + h * DK + i]);
    }
    // stage K tile: k_s[k][dk], tf32-rounded, pitch 36
    for (int idx = tid; idx < SK * 32; idx += 256) {
        int kk = idx >> 5, i = idx & 31;
        k_s[kk * KSP + i] = tf32f(kp[(b * SK + kk) * HID + h * DK + i]);
    }
    __syncthreads();

    // ---- Phase 1: tf32 MMA scores. Warp w owns k-rows [w*32, w*32+32). ----
    {
        const int m0 = w * 32;
        const unsigned* ksu = (const unsigned*)k_s;
        const unsigned* qtu = (const unsigned*)q_t;
        float dsc[2][4][4];
        #pragma unroll
        for (int mi = 0; mi < 2; mi++)
            #pragma unroll
            for (int nj = 0; nj < 4; nj++)
                #pragma unroll
                for (int r = 0; r < 4; r++) dsc[mi][nj][r] = 0.f;

        #pragma unroll
        for (int ks = 0; ks < 4; ks++) {
            const int k0 = ks * 8;
            unsigned a[2][4], bq[4][2];
            #pragma unroll
            for (int mi = 0; mi < 2; mi++) {
                const int ra = (m0 + mi * 16 + lr) * KSP + k0 + lc;
                const int rb = (m0 + mi * 16 + lr + 8) * KSP + k0 + lc;
                a[mi][0] = ksu[ra];
                a[mi][1] = ksu[rb];
                a[mi][2] = ksu[ra + 4];
                a[mi][3] = ksu[rb + 4];
            }
            #pragma unroll
            for (int nj = 0; nj < 4; nj++) {
                bq[nj][0] = qtu[(k0 + lc) * QP + nj * 8 + lr];
                bq[nj][1] = qtu[(k0 + 4 + lc) * QP + nj * 8 + lr];
            }
            #pragma unroll
            for (int mi = 0; mi < 2; mi++)
                #pragma unroll
                for (int nj = 0; nj < 4; nj++)
                    mma_tf32(dsc[mi][nj], a[mi], bq[nj]);
        }

        const float scale = 0.17677669529663687f;   // 1/sqrt(32)
        #pragma unroll
        for (int mi = 0; mi < 2; mi++)
            #pragma unroll
            for (int nj = 0; nj < 4; nj++) {
                const int row = m0 + mi * 16 + lr;
                const int col = nj * 8 + lc * 2;
                float2 e0, e1;
                e0.x = tf32f(__expf(dsc[mi][nj][0] * scale));
                e0.y = tf32f(__expf(dsc[mi][nj][1] * scale));
                e1.x = tf32f(__expf(dsc[mi][nj][2] * scale));
                e1.y = tf32f(__expf(dsc[mi][nj][3] * scale));
                *(float2*)(e_t + row * EP + col) = e0;
                *(float2*)(e_t + (row + 8) * EP + col) = e1;
            }
    }

    // ---- Phase 2: tf32 MMA contraction with register-prefetched vm. ----
    const int nb = w * 16;
    float d[2][2][4];
    #pragma unroll
    for (int i = 0; i < 2; i++)
        #pragma unroll
        for (int j = 0; j < 2; j++)
            #pragma unroll
            for (int r = 0; r < 4; r++) d[i][j][r] = 0.f;

    const unsigned* eu = (const unsigned*)e_t;
    const unsigned* vu = (const unsigned*)k_s;   // vm reuses K-tile region
    float* vmf = k_s;

    const int p_lk = tid >> 5;      // this thread's k-row stride base
    const int p_d2 = tid & 31;

    // prefetch chunk 0
    float2 pv[8]; int2 pm[8];
    #pragma unroll
    for (int it = 0; it < 8; it++) {
        int gbase = (b * SK + p_lk + it * 8) * DIM + p_d2 * 2;
        pv[it] = *(const float2*)(value + gbase);
        pm[it] = *(const int2*)(mask + gbase);
    }

    #pragma unroll 1
    for (int c = 0; c < 4; c++) {
        __syncthreads();                    // phase-1 k_s reads / prev chunk consumed
        // transform + store prefetched chunk
        #pragma unroll
        for (int it = 0; it < 8; it++) {
            int lk = p_lk + it * 8;
            float4 wv;
            wv.x = pm[it].x ? tf32f(pv[it].x) : 0.f;  wv.y = pm[it].x ? 1.f : 0.f;
            wv.z = pm[it].y ? tf32f(pv[it].y) : 0.f;  wv.w = pm[it].y ? 1.f : 0.f;
            *(float4*)(vmf + lk * VP + p_d2 * 4) = wv;
        }
        __syncthreads();
        // prefetch next chunk (latency overlaps the MMA loop below)
        if (c < 3) {
            #pragma unroll
            for (int it = 0; it < 8; it++) {
                int gbase = (b * SK + (c + 1) * 64 + p_lk + it * 8) * DIM + p_d2 * 2;
                pv[it] = *(const float2*)(value + gbase);
                pm[it] = *(const int2*)(mask + gbase);
            }
        }

        #pragma unroll
        for (int ks = 0; ks < 8; ks++) {
            const int k0 = c * 64 + ks * 8;
            unsigned a[2][4];
            const int ea = (k0 + lc) * EP + lr;
            const int eb = (k0 + 4 + lc) * EP + lr;
            #pragma unroll
            for (int i = 0; i < 2; i++) {
                a[i][0] = eu[ea + i * 16];
                a[i][1] = eu[ea + i * 16 + 8];
                a[i][2] = eu[eb + i * 16];
                a[i][3] = eu[eb + i * 16 + 8];
            }
            unsigned bf[2][2];
            const int ba = (ks * 8 + lc) * VP + nb + lr;
            #pragma unroll
            for (int j = 0; j < 2; j++) {
                bf[j][0] = vu[ba + j * 8];
                bf[j][1] = vu[ba + j * 8 + 4 * VP];
            }
            #pragma unroll
            for (int i = 0; i < 2; i++)
                #pragma unroll
                for (int j = 0; j < 2; j++)
                    mma_tf32(d[i][j], a[i], bf[j]);
        }
    }

    // Epilogue: x = num/den (den==0 fallback: mean(value))
    #pragma unroll
    for (int j = 0; j < 2; j++) {
        const int ch = w * 8 + j * 4 + lc;
        bool bad = false;
        #pragma unroll
        for (int i = 0; i < 2; i++)
            if (d[i][j][1] == 0.f || d[i][j][3] == 0.f) bad = true;
        float vs = 0.f;
        if (bad) {
            for (int kk = 0; kk < SK; kk++)
                vs += value[(b * SK + kk) * DIM + ch];
            vs *= (1.0f / 256.0f);
        }
        #pragma unroll
        for (int i = 0; i < 2; i++) {
            const int ra = i * 16 + lr;
            const int rb = ra + 8;
            float xa = (d[i][j][1] > 0.f) ? (d[i][j][0] / d[i][j][1]) : vs;
            float xb = (d[i][j][3] > 0.f) ? (d[i][j][2] / d[i][j][3]) : vs;
            xout[(b * SQ + q0 + ra) * (H * DIM) + h * DIM + ch] = xa;
            xout[(b * SQ + q0 + rb) * (H * DIM) + h * DIM + ch] = xb;
        }
    }
}

// ---------------------------------------------------------------------------
extern "C" void kernel_launch(void* const* d_in, const int* in_sizes, int n_in,
                              void* d_out, int out_size) {
    const float* query = (const float*)d_in[0];
    const float* key   = (const float*)d_in[1];
    const float* value = (const float*)d_in[2];
    const int*   mask  = (const int*)  d_in[3];
    const float* Wq    = (const float*)d_in[4];
    const float* bq    = (const float*)d_in[5];
    const float* Wk    = (const float*)d_in[6];
    const float* bk    = (const float*)d_in[7];
    const float* Wo    = (const float*)d_in[8];
    const float* bo    = (const float*)d_in[9];
    float* out = (float*)d_out;

    float* qp; cudaGetSymbolAddress((void**)&qp, g_qp);
    float* kp; cudaGetSymbolAddress((void**)&kp, g_kp);
    float* xb; cudaGetSymbolAddress((void**)&xb, g_x);

    const int smem_attn = (32 * QP + SK * EP + SK * KSP) * (int)sizeof(float); // 78.3 KB
    cudaFuncSetAttribute(attn_kernel, cudaFuncAttributeMaxDynamicSharedMemorySize, smem_attn);

    // Q (2048x128x128) + K (4096x128x128) projection: 384 blocks (SIMT, measured best)
    qk_proj_kernel<<<384, 128>>>(query, Wq, bq, qp, key, Wk, bk, kp);
    // fused attention: 256 blocks
    attn_kernel<<<B * H * (SQ / QT), 256, smem_attn>>>(qp, kp, value, mask, xb);
    // output projection: 2048x128x256, 256 blocks (fills the chip)
    o_proj_kernel<<<256, 128>>>(xb, Wo, bo, out);
}